// round 12
// baseline (speedup 1.0000x reference)
#include <cuda_runtime.h>
#include <cstdint>

// Problem constants (fixed shape instance)
constexpr int B = 64;
constexpr int Q = 1024;
constexpr int N = 2048;
constexpr int C = 2048;
constexpr int P = 512;
constexpr int W = 256;
constexpr int HALF = W / 2;

// GEMM tiling (best measured): 64b x 64j x 64k, grid (8, 32)
constexpr int KC  = 64;
constexpr int KS  = C / KC;   // 32
constexpr int JT  = 64;
constexpr int NJT = P / JT;   // 8
constexpr int SST = 68;       // smem row stride (floats): conflict-free, 16B-aligned

// Scratch (__device__ globals: allocation-free rule)
__device__ float d_Hpart[KS * B * P];   // 4 MB split partials (L2-resident)
__device__ float d_partial[B * NJT];    // per-(b, j-tile) v_p.tanh partial dots

__device__ __forceinline__ unsigned long long pk2(float lo, float hi) {
    unsigned long long r;
    asm("mov.b64 %0, {%1, %2};" : "=l"(r) : "f"(lo), "f"(hi));
    return r;
}
__device__ __forceinline__ void fma2(unsigned long long& d,
                                     unsigned long long a, unsigned long long b) {
    asm("fma.rn.f32x2 %0, %1, %2, %0;" : "+l"(d) : "l"(a), "l"(b));
}

// ---------------------------------------------------------------------------
// K1 (unchanged, 8.32us measured): Hpart[ks][b][j] = sum_k c_t[b,k]*w_p[j,k]
// grid (NJT, KS), 256 threads. Thread tile 4b x 4j, f32x2 over j-pairs.
// ---------------------------------------------------------------------------
__global__ __launch_bounds__(256, 4) void gemm_kernel(
    const float* __restrict__ c_t, const float* __restrict__ w_p)
{
    __shared__ float sc[KC][SST];   // k-major c tile: 64k x 64b
    __shared__ float sw[KC][SST];   // k-major w tile: 64k x 64j

    const int jt = blockIdx.x;
    const int ks = blockIdx.y;
    const int k0 = ks * KC;
    const int t  = threadIdx.x;
    const int kl  = t & 63;
    const int grp = t >> 6;          // 0..3

#pragma unroll
    for (int it = 0; it < 4; it++) {
        int bq = grp * 4 + it;       // 0..15
        const float* cr = c_t + (size_t)(bq * 4) * C + k0 + kl;
        float v0 = __ldg(cr);
        float v1 = __ldg(cr + C);
        float v2 = __ldg(cr + 2 * C);
        float v3 = __ldg(cr + 3 * C);
        *reinterpret_cast<float4*>(&sc[kl][bq * 4]) = make_float4(v0, v1, v2, v3);
    }
#pragma unroll
    for (int it = 0; it < 4; it++) {
        int jq = grp * 4 + it;       // 0..15
        const float* wr = w_p + (size_t)(jt * JT + jq * 4) * C + k0 + kl;
        float v0 = __ldg(wr);
        float v1 = __ldg(wr + C);
        float v2 = __ldg(wr + 2 * C);
        float v3 = __ldg(wr + 3 * C);
        *reinterpret_cast<float4*>(&sw[kl][jq * 4]) = make_float4(v0, v1, v2, v3);
    }
    __syncthreads();

    const int jg = t & 15;
    const int bg = t >> 4;
    const int b0 = bg * 4;
    const int j0 = jg * 4;

    unsigned long long acc[4][2];    // [bb][j-pair]
#pragma unroll
    for (int bb = 0; bb < 4; bb++) { acc[bb][0] = 0ull; acc[bb][1] = 0ull; }

#pragma unroll 8
    for (int k = 0; k < KC; k++) {
        float4 ca = *reinterpret_cast<const float4*>(&sc[k][b0]);
        ulonglong2 wv = *reinterpret_cast<const ulonglong2*>(&sw[k][j0]);
        unsigned long long cd0 = pk2(ca.x, ca.x);
        unsigned long long cd1 = pk2(ca.y, ca.y);
        unsigned long long cd2 = pk2(ca.z, ca.z);
        unsigned long long cd3 = pk2(ca.w, ca.w);
        fma2(acc[0][0], cd0, wv.x); fma2(acc[0][1], cd0, wv.y);
        fma2(acc[1][0], cd1, wv.x); fma2(acc[1][1], cd1, wv.y);
        fma2(acc[2][0], cd2, wv.x); fma2(acc[2][1], cd2, wv.y);
        fma2(acc[3][0], cd3, wv.x); fma2(acc[3][1], cd3, wv.y);
    }

#pragma unroll
    for (int bb = 0; bb < 4; bb++) {
        size_t row = ((size_t)ks * B + (b0 + bb)) * P + jt * JT + j0;
        *reinterpret_cast<ulonglong2*>(&d_Hpart[row]) =
            make_ulonglong2(acc[bb][0], acc[bb][1]);
    }
}

// ---------------------------------------------------------------------------
// K2 (unchanged): per (b, j-tile): Hsum = sum_ks Hpart; partial = v_p.tanh dot
// grid 512 (b = bid>>3, jt = bid&7), 256 thr.
// ---------------------------------------------------------------------------
__global__ __launch_bounds__(256) void reduce_head_kernel(
    const float* __restrict__ v_p)
{
    const int b  = blockIdx.x >> 3;
    const int jt = blockIdx.x & 7;
    const int t  = threadIdx.x;
    const int jq = t & 15;           // j-quad within 64-j tile
    const int g  = t >> 4;           // 0..15 ks-group

    float4 s = make_float4(0.f, 0.f, 0.f, 0.f);
#pragma unroll
    for (int i = 0; i < 2; i++) {
        int ks = g + 16 * i;
        float4 h = *reinterpret_cast<const float4*>(
            &d_Hpart[((size_t)ks * B + b) * P + jt * JT + jq * 4]);
        s.x += h.x; s.y += h.y; s.z += h.z; s.w += h.w;
    }
    __shared__ float4 hs[16][16];
    hs[g][jq] = s;
    __syncthreads();

    __shared__ float red[2];
    if (t < 64) {
        int quad = t >> 2, c = t & 3;
        float sum = 0.f;
#pragma unroll
        for (int g2 = 0; g2 < 16; g2++)
            sum += reinterpret_cast<const float*>(&hs[g2][quad])[c];
        float part = __ldg(v_p + jt * JT + t) * tanhf(sum);
#pragma unroll
        for (int o = 16; o > 0; o >>= 1)
            part += __shfl_down_sync(0xffffffffu, part, o);
        if ((t & 31) == 0) red[t >> 5] = part;
    }
    __syncthreads();
    if (t == 0) d_partial[b * NJT + jt] = red[0] + red[1];
}

// ---------------------------------------------------------------------------
// K3 v3: window sum, 4 rows per warp, __ldcs streaming loads.
// s_t[b,q] = sum_w g[b,w] * q_i[b, q, base + w]
// grid (Q/32 = 32, B) = 2048 blocks, 256 thr (8 warps x 4 rows).
// ---------------------------------------------------------------------------
__global__ __launch_bounds__(256) void window_sum_kernel(
    const float* __restrict__ q_i, float* __restrict__ out)
{
    __shared__ float g[W];
    __shared__ float s_pt;
    __shared__ int   s_base;

    const int b = blockIdx.y;
    const int t = threadIdx.x;

    // head recompute (deterministic, identical for all blocks of batch b)
    if (t == 0) {
        float x = 0.f;
#pragma unroll
        for (int i = 0; i < NJT; i++) x += d_partial[b * NJT + i];
        float loc = 1.f / (1.f + expf(-x));
        float pt  = loc * (float)(N - 1);      // loc * 2047
        int   p   = (int)rintf(pt);            // round-half-even == jnp.round
        int base = p - HALF;
        if (base < 0) base = 0;
        if (base > N - W) base = N - W;
        s_pt = pt; s_base = base;
    }
    __syncthreads();

    {   // gaussian weights (blockDim == W)
        int n = s_base + t;
        float d = ((float)n - s_pt) * (1.0f / (float)HALF);
        g[t] = expf(-2.f * d * d);
    }
    __syncthreads();

    const int warp = t >> 5, lane = t & 31;
    const int q = blockIdx.x * 32 + warp * 4;
    const float* row0 = q_i + ((size_t)b * Q + q) * N + s_base;

    float gw[8];
#pragma unroll
    for (int i = 0; i < 8; i++) gw[i] = g[lane + 32 * i];

    float x0[8], x1[8], x2[8], x3[8];
#pragma unroll
    for (int i = 0; i < 8; i++) x0[i] = __ldcs(row0 + lane + 32 * i);
#pragma unroll
    for (int i = 0; i < 8; i++) x1[i] = __ldcs(row0 + N + lane + 32 * i);
#pragma unroll
    for (int i = 0; i < 8; i++) x2[i] = __ldcs(row0 + 2 * N + lane + 32 * i);
#pragma unroll
    for (int i = 0; i < 8; i++) x3[i] = __ldcs(row0 + 3 * N + lane + 32 * i);

    float a0 = 0.f, a1 = 0.f, a2 = 0.f, a3 = 0.f;
#pragma unroll
    for (int i = 0; i < 8; i++) {
        a0 += gw[i] * x0[i];
        a1 += gw[i] * x1[i];
        a2 += gw[i] * x2[i];
        a3 += gw[i] * x3[i];
    }

#pragma unroll
    for (int o = 16; o > 0; o >>= 1) {
        a0 += __shfl_down_sync(0xffffffffu, a0, o);
        a1 += __shfl_down_sync(0xffffffffu, a1, o);
        a2 += __shfl_down_sync(0xffffffffu, a2, o);
        a3 += __shfl_down_sync(0xffffffffu, a3, o);
    }
    if (lane == 0) {
        float* ob = out + (size_t)b * Q + q;
        ob[0] = a0; ob[1] = a1; ob[2] = a2; ob[3] = a3;
    }
}

// ---------------------------------------------------------------------------
extern "C" void kernel_launch(void* const* d_in, const int* in_sizes, int n_in,
                              void* d_out, int out_size)
{
    const float* q_i = (const float*)d_in[0];  // (B,Q,N)
    const float* c_t = (const float*)d_in[1];  // (B,C)
    // d_in[2] = w_a : cancels (softmax over singleton axis == 1)
    const float* w_p = (const float*)d_in[3];  // (P,C)
    const float* v_p = (const float*)d_in[4];  // (1,P)
    float* out = (float*)d_out;                // (B,Q)

    gemm_kernel<<<dim3(NJT, KS), 256>>>(c_t, w_p);
    reduce_head_kernel<<<B * NJT, 256>>>(v_p);
    window_sum_kernel<<<dim3(Q / 32, B), 256>>>(q_i, out);
}

// round 13
// speedup vs baseline: 1.3271x; 1.3271x over previous
#include <cuda_runtime.h>
#include <cstdint>

// Problem constants (fixed shape instance)
constexpr int B = 64;
constexpr int Q = 1024;
constexpr int N = 2048;
constexpr int C = 2048;
constexpr int P = 512;
constexpr int W = 256;
constexpr int HALF = W / 2;

// GEMM tiling (best measured): 64b x 64j x 64k, grid (8, 32)
constexpr int KC  = 64;
constexpr int KS  = C / KC;   // 32
constexpr int JT  = 64;
constexpr int NJT = P / JT;   // 8
constexpr int SST = 68;       // smem row stride (floats): conflict-free, 16B-aligned

// Scratch (__device__ globals: allocation-free rule)
__device__ float d_Hpart[KS * B * P];   // 4 MB split partials (L2-resident)
__device__ float d_partial[B * NJT];    // per-(b, j-tile) v_p.tanh partial dots

__device__ __forceinline__ unsigned long long pk2(float lo, float hi) {
    unsigned long long r;
    asm("mov.b64 %0, {%1, %2};" : "=l"(r) : "f"(lo), "f"(hi));
    return r;
}
__device__ __forceinline__ void fma2(unsigned long long& d,
                                     unsigned long long a, unsigned long long b) {
    asm("fma.rn.f32x2 %0, %1, %2, %0;" : "+l"(d) : "l"(a), "l"(b));
}

// ---------------------------------------------------------------------------
// K1 (8.32us measured): Hpart[ks][b][j] = sum_k c_t[b,k]*w_p[j,k]
// grid (NJT, KS), 256 threads. Thread tile 4b x 4j, f32x2 over j-pairs.
// ---------------------------------------------------------------------------
__global__ __launch_bounds__(256, 4) void gemm_kernel(
    const float* __restrict__ c_t, const float* __restrict__ w_p)
{
    __shared__ float sc[KC][SST];   // k-major c tile: 64k x 64b
    __shared__ float sw[KC][SST];   // k-major w tile: 64k x 64j

    const int jt = blockIdx.x;
    const int ks = blockIdx.y;
    const int k0 = ks * KC;
    const int t  = threadIdx.x;
    const int kl  = t & 63;
    const int grp = t >> 6;          // 0..3

#pragma unroll
    for (int it = 0; it < 4; it++) {
        int bq = grp * 4 + it;       // 0..15
        const float* cr = c_t + (size_t)(bq * 4) * C + k0 + kl;
        float v0 = __ldg(cr);
        float v1 = __ldg(cr + C);
        float v2 = __ldg(cr + 2 * C);
        float v3 = __ldg(cr + 3 * C);
        *reinterpret_cast<float4*>(&sc[kl][bq * 4]) = make_float4(v0, v1, v2, v3);
    }
#pragma unroll
    for (int it = 0; it < 4; it++) {
        int jq = grp * 4 + it;       // 0..15
        const float* wr = w_p + (size_t)(jt * JT + jq * 4) * C + k0 + kl;
        float v0 = __ldg(wr);
        float v1 = __ldg(wr + C);
        float v2 = __ldg(wr + 2 * C);
        float v3 = __ldg(wr + 3 * C);
        *reinterpret_cast<float4*>(&sw[kl][jq * 4]) = make_float4(v0, v1, v2, v3);
    }
    __syncthreads();

    const int jg = t & 15;
    const int bg = t >> 4;
    const int b0 = bg * 4;
    const int j0 = jg * 4;

    unsigned long long acc[4][2];    // [bb][j-pair]
#pragma unroll
    for (int bb = 0; bb < 4; bb++) { acc[bb][0] = 0ull; acc[bb][1] = 0ull; }

#pragma unroll 8
    for (int k = 0; k < KC; k++) {
        float4 ca = *reinterpret_cast<const float4*>(&sc[k][b0]);
        ulonglong2 wv = *reinterpret_cast<const ulonglong2*>(&sw[k][j0]);
        unsigned long long cd0 = pk2(ca.x, ca.x);
        unsigned long long cd1 = pk2(ca.y, ca.y);
        unsigned long long cd2 = pk2(ca.z, ca.z);
        unsigned long long cd3 = pk2(ca.w, ca.w);
        fma2(acc[0][0], cd0, wv.x); fma2(acc[0][1], cd0, wv.y);
        fma2(acc[1][0], cd1, wv.x); fma2(acc[1][1], cd1, wv.y);
        fma2(acc[2][0], cd2, wv.x); fma2(acc[2][1], cd2, wv.y);
        fma2(acc[3][0], cd3, wv.x); fma2(acc[3][1], cd3, wv.y);
    }

#pragma unroll
    for (int bb = 0; bb < 4; bb++) {
        size_t row = ((size_t)ks * B + (b0 + bb)) * P + jt * JT + j0;
        *reinterpret_cast<ulonglong2*>(&d_Hpart[row]) =
            make_ulonglong2(acc[bb][0], acc[bb][1]);
    }

#if __CUDA_ARCH__ >= 900
    cudaTriggerProgrammaticLaunchCompletion();
#endif
}

// ---------------------------------------------------------------------------
// K2: per (b, j-tile): Hsum = sum_ks Hpart; partial = v_p.tanh dot
// grid 512 (b = bid>>3, jt = bid&7), 256 thr. PDL consumer of K1.
// ---------------------------------------------------------------------------
__global__ __launch_bounds__(256) void reduce_head_kernel(
    const float* __restrict__ v_p)
{
    const int b  = blockIdx.x >> 3;
    const int jt = blockIdx.x & 7;
    const int t  = threadIdx.x;
    const int jq = t & 15;           // j-quad within 64-j tile
    const int g  = t >> 4;           // 0..15 ks-group

    // load v_p early (independent of K1), then wait for K1's stores
    float vp = (t < 64) ? __ldg(v_p + jt * JT + t) : 0.f;

#if __CUDA_ARCH__ >= 900
    cudaGridDependencySynchronize();
#endif

    float4 s = make_float4(0.f, 0.f, 0.f, 0.f);
#pragma unroll
    for (int i = 0; i < 2; i++) {
        int ks = g + 16 * i;
        float4 h = *reinterpret_cast<const float4*>(
            &d_Hpart[((size_t)ks * B + b) * P + jt * JT + jq * 4]);
        s.x += h.x; s.y += h.y; s.z += h.z; s.w += h.w;
    }
    __shared__ float4 hs[16][16];
    hs[g][jq] = s;
    __syncthreads();

    __shared__ float red[2];
    if (t < 64) {
        int quad = t >> 2, c = t & 3;
        float sum = 0.f;
#pragma unroll
        for (int g2 = 0; g2 < 16; g2++)
            sum += reinterpret_cast<const float*>(&hs[g2][quad])[c];
        float part = vp * tanhf(sum);
#pragma unroll
        for (int o = 16; o > 0; o >>= 1)
            part += __shfl_down_sync(0xffffffffu, part, o);
        if ((t & 31) == 0) red[t >> 5] = part;
    }
    __syncthreads();
    if (t == 0) d_partial[b * NJT + jt] = red[0] + red[1];

#if __CUDA_ARCH__ >= 900
    cudaTriggerProgrammaticLaunchCompletion();
#endif
}

// ---------------------------------------------------------------------------
// K3 (R11 config — best measured): window sum, 2 rows per warp, __ldcs.
// s_t[b,q] = sum_w g[b,w] * q_i[b, q, base + w]
// grid (Q/16 = 64, B) = 4096 blocks, 256 thr. PDL consumer of K2.
// ---------------------------------------------------------------------------
__global__ __launch_bounds__(256) void window_sum_kernel(
    const float* __restrict__ q_i, float* __restrict__ out)
{
    __shared__ float g[W];
    __shared__ float s_pt;
    __shared__ int   s_base;

    const int b = blockIdx.y;
    const int t = threadIdx.x;
    const int warp = t >> 5, lane = t & 31;
    const int q = blockIdx.x * 16 + warp * 2;

#if __CUDA_ARCH__ >= 900
    cudaGridDependencySynchronize();
#endif

    // head recompute (deterministic, identical for all blocks of batch b)
    if (t == 0) {
        float x = 0.f;
#pragma unroll
        for (int i = 0; i < NJT; i++) x += d_partial[b * NJT + i];
        float loc = 1.f / (1.f + expf(-x));
        float pt  = loc * (float)(N - 1);      // loc * 2047
        int   p   = (int)rintf(pt);            // round-half-even == jnp.round
        int base = p - HALF;
        if (base < 0) base = 0;
        if (base > N - W) base = N - W;
        s_pt = pt; s_base = base;
    }
    __syncthreads();

    {   // gaussian weights (blockDim == W)
        int n = s_base + t;
        float d = ((float)n - s_pt) * (1.0f / (float)HALF);
        g[t] = expf(-2.f * d * d);
    }
    __syncthreads();

    const float* row0 = q_i + ((size_t)b * Q + q) * N + s_base;
    const float* row1 = row0 + N;

    float gw[8];
#pragma unroll
    for (int i = 0; i < 8; i++) gw[i] = g[lane + 32 * i];

    float x0[8], x1[8];
#pragma unroll
    for (int i = 0; i < 8; i++) x0[i] = __ldcs(row0 + lane + 32 * i);
#pragma unroll
    for (int i = 0; i < 8; i++) x1[i] = __ldcs(row1 + lane + 32 * i);

    float a0 = 0.f, a1 = 0.f;
#pragma unroll
    for (int i = 0; i < 8; i++) { a0 += gw[i] * x0[i]; a1 += gw[i] * x1[i]; }

#pragma unroll
    for (int o = 16; o > 0; o >>= 1) {
        a0 += __shfl_down_sync(0xffffffffu, a0, o);
        a1 += __shfl_down_sync(0xffffffffu, a1, o);
    }
    if (lane == 0) {
        out[(size_t)b * Q + q]     = a0;
        out[(size_t)b * Q + q + 1] = a1;
    }
}

// ---------------------------------------------------------------------------
extern "C" void kernel_launch(void* const* d_in, const int* in_sizes, int n_in,
                              void* d_out, int out_size)
{
    const float* q_i = (const float*)d_in[0];  // (B,Q,N)
    const float* c_t = (const float*)d_in[1];  // (B,C)
    // d_in[2] = w_a : cancels (softmax over singleton axis == 1)
    const float* w_p = (const float*)d_in[3];  // (P,C)
    const float* v_p = (const float*)d_in[4];  // (1,P)
    float* out = (float*)d_out;                // (B,Q)

    gemm_kernel<<<dim3(NJT, KS), 256>>>(c_t, w_p);

    // K2, K3 as PDL consumers: launch overlaps producer's tail; the
    // device-side cudaGridDependencySynchronize() gates dependent reads.
    cudaLaunchAttribute attr[1];
    attr[0].id = cudaLaunchAttributeProgrammaticStreamSerialization;
    attr[0].val.programmaticStreamSerializationAllowed = 1;

    {
        cudaLaunchConfig_t cfg{};
        cfg.gridDim  = dim3(B * NJT);
        cfg.blockDim = dim3(256);
        cfg.attrs    = attr;
        cfg.numAttrs = 1;
        cudaLaunchKernelEx(&cfg, reduce_head_kernel, v_p);
    }
    {
        cudaLaunchConfig_t cfg{};
        cfg.gridDim  = dim3(Q / 16, B);
        cfg.blockDim = dim3(256);
        cfg.attrs    = attr;
        cfg.numAttrs = 1;
        cudaLaunchKernelEx(&cfg, window_sum_kernel, q_i, out);
    }
}